// round 12
// baseline (speedup 1.0000x reference)
#include <cuda_runtime.h>
#include <math.h>

// FullPairwise neighbor list: M=8 molecules, N=1024 atoms, cutoff 5.2.
// Output (float32 buffer): [2, P] flat atom indices written as floats
// (row 0: i's, row 1: j's), pairs ordered lexicographically by
// (molecule, i, j); trailing elements (incl. the zeros(3) output) zeroed.
//
// SINGLE persistent kernel, 256 all-resident blocks + software grid barrier.
// This revision attacks the serial path around the barrier:
//  - whole output pre-zeroed BEFORE the barrier (no post-barrier tail pass)
//  - no post-barrier __syncthreads: every warp redundantly reduces the 256
//    block sums itself (coalesced, L2-hit)
//  - emit prefix work hoisted pre-barrier.
// Cutoff: sqrtf is correctly rounded & monotone, so sqrtf(d2) <= 5.2f
//   <=>  d2 <= 27.039999008178710938f (0x41D851EB) exactly (NaN -> false).

#define NMOL 8
#define NATM 1024
#define NROWS 8192
#define NBLK 256
#define NTHR 512
#define C2_EXACT 27.039999008178710938f   // largest f32 with sqrtf(x) <= 5.2f

__device__ int g_blkSum[NBLK];
__device__ unsigned g_arrive;    // monotonic across launches (zero-init once)
__device__ unsigned g_epoch;     // incremented by last arrival of each launch

__device__ __forceinline__ unsigned valid_mask(int iloc, int c) {
    const int ls = iloc + 1 - c * 32;     // first j > i within chunk c
    if (ls <= 0) return 0xFFFFFFFFu;
    return (ls >= 32) ? 0u : (0xFFFFFFFFu << ls);
}

__device__ __forceinline__ int warp_excl_scan(int v, int c) {
    int s = v;
#pragma unroll
    for (int off = 1; off < 32; off <<= 1) {
        int t = __shfl_up_sync(0xFFFFFFFFu, s, off);
        if (c >= off) s += t;
    }
    return s - v;
}

__global__ void __launch_bounds__(NTHR, 2)
fused_kernel(const int* __restrict__ species,
             const float* __restrict__ coords,
             float* __restrict__ out, int out_size) {
    __shared__ float4 s4[1056];       // +1-per-32 padded: idx = a + (a>>5)
    __shared__ int s_rowCnt[32];
    __shared__ int s_rowOff[32];

    const unsigned FULL = 0xFFFFFFFFu;
    const int b = blockIdx.x;
    const int tid = threadIdx.x;
    const int w = tid >> 5;           // warp 0..15, handles rows 2w, 2w+1
    const int c = tid & 31;           // lane = chunk

    const int grow0 = b * 32 + 2 * w; // global flat rows (== output i values)
    const int mb = grow0 & ~(NATM - 1);
    const int iloc0 = grow0 & (NATM - 1);
    const int iloc1 = iloc0 + 1;

    // ---- pre-zero whole output (pairs overwrite after the barrier) ----
    {
        const int gtid = b * NTHR + tid;
        for (int idx = gtid; idx < out_size; idx += NBLK * NTHR)
            out[idx] = 0.0f;
    }

    // ---- stage molecule coords (NaN-fill padded atoms) ----
    for (int a = tid; a < NATM; a += NTHR) {
        const int ga = mb + a;
        const float* cp = coords + (size_t)ga * 3;
        float x = cp[0], y = cp[1], z = cp[2];
        if (species[ga] == -1) {
            const float nanv = __int_as_float(0x7fc00000);
            x = nanv; y = nanv; z = nanv;
        }
        s4[a + (a >> 5)] = make_float4(x, y, z, 0.0f);
    }
    __syncthreads();

    // ---- my two row coordinates ----
    const float4 ci0 = s4[iloc0 + (iloc0 >> 5)];
    const float4 ci1 = s4[iloc1 + (iloc1 >> 5)];
    const unsigned valid0 = valid_mask(iloc0, c);
    const unsigned valid1 = valid_mask(iloc1, c);

    // ---- phase A: 32 LDS.128, 64 pair tests -> two register bitmasks ----
    unsigned mask0 = 0u, mask1 = 0u;
    const int sbase = c * 33;         // padded chunk base (conflict-free)
#pragma unroll 4
    for (int l = 0; l < 32; l++) {
        const float4 cj = s4[sbase + l];
        {
            float dx = ci0.x - cj.x, dy = ci0.y - cj.y, dz = ci0.z - cj.z;
            float d2 = fmaf(dz, dz, fmaf(dy, dy, dx * dx));
            mask0 |= ((unsigned)(d2 <= C2_EXACT)) << l;   // NaN -> false
        }
        {
            float dx = ci1.x - cj.x, dy = ci1.y - cj.y, dz = ci1.z - cj.z;
            float d2 = fmaf(dz, dz, fmaf(dy, dy, dx * dx));
            mask1 |= ((unsigned)(d2 <= C2_EXACT)) << l;
        }
    }
    mask0 &= valid0;
    mask1 &= valid1;

    // ---- per-row counts + block-local exclusive row offsets ----
    const int pc0 = __popc(mask0);
    const int pc1 = __popc(mask1);
    const int rs0 = __reduce_add_sync(FULL, pc0);
    const int rs1 = __reduce_add_sync(FULL, pc1);
    if (c == 0) { s_rowCnt[2 * w] = rs0; s_rowCnt[2 * w + 1] = rs1; }
    __syncthreads();
    if (w == 0) {
        const int v = s_rowCnt[c];
        const int e = warp_excl_scan(v, c);
        s_rowOff[c] = e;
        if (c == 31) g_blkSum[b] = e + v;      // block total
    }
    __syncthreads();

    // ---- hoist emit prefix work (independent of barrier results) ----
    const int lane_off0 = warp_excl_scan(pc0, c);   // within-row lane offsets
    const int lane_off1 = warp_excl_scan(pc1, c);
    const int pre_o0 = s_rowOff[2 * w] + lane_off0;
    const int pre_o1 = s_rowOff[2 * w + 1] + lane_off1;

    // ---- grid barrier (monotonic epoch: safe across graph replays) ----
    __threadfence();                  // release: zeros + g_blkSum before arrive
    __syncthreads();
    if (tid == 0) {
        unsigned my = atomicAdd(&g_arrive, 1);
        unsigned target = my + 1;
        if ((target & (NBLK - 1)) == 0u)   // last arrival of this launch
            atomicAdd(&g_epoch, 1);
        while ((int)(NBLK * (*(volatile unsigned*)&g_epoch) - target) < 0)
            __nanosleep(32);
        __threadfence();
    }
    __syncthreads();

    // ---- phase B: every warp redundantly reduces the 256 block sums ----
    int bsum = 0, tsum = 0;
#pragma unroll
    for (int q = 0; q < NBLK / 32; q++) {
        const int k = q * 32 + c;
        const int v = __ldcg(&g_blkSum[k]);
        tsum += v;
        if (k < b) bsum += v;
    }
    const int blockBase = __reduce_add_sync(FULL, bsum);
    const int total = __reduce_add_sync(FULL, tsum);

    // ---- phase C: emit pairs (two rows per warp); tail already zeroed ----
    const int jb = mb + c * 32;
    if (mask0) {
        int o = blockBase + pre_o0;
        const float rowf = (float)grow0;
        unsigned mm = mask0;
        while (mm) {
            const int l = __ffs(mm) - 1;
            mm &= mm - 1;
            out[o] = rowf;
            out[total + o] = (float)(jb + l);
            o++;
        }
    }
    if (mask1) {
        int o = blockBase + pre_o1;
        const float rowf = (float)(grow0 + 1);
        unsigned mm = mask1;
        while (mm) {
            const int l = __ffs(mm) - 1;
            mm &= mm - 1;
            out[o] = rowf;
            out[total + o] = (float)(jb + l);
            o++;
        }
    }
}

extern "C" void kernel_launch(void* const* d_in, const int* in_sizes, int n_in,
                              void* d_out, int out_size) {
    const int* species = (const int*)d_in[0];
    const float* coords = (const float*)d_in[1];
    float* out = (float*)d_out;

    fused_kernel<<<NBLK, NTHR>>>(species, coords, out, out_size);
}

// round 13
// speedup vs baseline: 1.1350x; 1.1350x over previous
#include <cuda_runtime.h>
#include <math.h>

// FullPairwise neighbor list: M=8 molecules, N=1024 atoms, cutoff 5.2.
// Output (float32 buffer): [2, P] flat atom indices written as floats
// (row 0: i's, row 1: j's), pairs ordered lexicographically by
// (molecule, i, j); trailing elements (incl. the zeros(3) output) zeroed.
//
// SINGLE persistent kernel, 128 all-resident blocks (<=1 per SM, uniform)
// + software grid barrier. Warp = 2 rows (register-blocked LDS.128 reuse).
// Tail zeroing is post-barrier (pre-barrier fence-with-inflight-STG was a
// measured regression). Cutoff: sqrtf correctly rounded & monotone =>
//   sqrtf(d2) <= 5.2f  <=>  d2 <= 27.039999008178710938f (NaN -> false).

#define NMOL 8
#define NATM 1024
#define NROWS 8192
#define NBLK 128
#define NTHR 1024
#define ROWS_PER_BLK 64
#define C2_EXACT 27.039999008178710938f   // largest f32 with sqrtf(x) <= 5.2f

__device__ int g_blkSum[NBLK];
__device__ unsigned g_arrive;    // monotonic across launches (zero-init once)
__device__ unsigned g_epoch;     // incremented by last arrival of each launch

__device__ __forceinline__ unsigned valid_mask(int iloc, int c) {
    const int ls = iloc + 1 - c * 32;     // first j > i within chunk c
    if (ls <= 0) return 0xFFFFFFFFu;
    return (ls >= 32) ? 0u : (0xFFFFFFFFu << ls);
}

__device__ __forceinline__ int warp_excl_scan(int v, int c) {
    int s = v;
#pragma unroll
    for (int off = 1; off < 32; off <<= 1) {
        int t = __shfl_up_sync(0xFFFFFFFFu, s, off);
        if (c >= off) s += t;
    }
    return s - v;
}

__global__ void __launch_bounds__(NTHR, 1)
fused_kernel(const int* __restrict__ species,
             const float* __restrict__ coords,
             float* __restrict__ out, int out_size) {
    __shared__ float4 s4[1056];       // +1-per-32 padded: idx = a + (a>>5)
    __shared__ int s_rowCnt[ROWS_PER_BLK];
    __shared__ int s_rowOff[ROWS_PER_BLK];

    const unsigned FULL = 0xFFFFFFFFu;
    const int b = blockIdx.x;
    const int tid = threadIdx.x;
    const int w = tid >> 5;           // warp 0..31, handles rows 2w, 2w+1
    const int c = tid & 31;           // lane = chunk

    const int grow0 = b * ROWS_PER_BLK + 2 * w;  // global flat rows
    const int mb = grow0 & ~(NATM - 1);          // molecule base (blocks never straddle)
    const int iloc0 = grow0 & (NATM - 1);
    const int iloc1 = iloc0 + 1;

    // ---- stage molecule coords (NaN-fill padded atoms) ----
    {
        const int a = tid;            // NTHR == NATM: one atom per thread
        const int ga = mb + a;
        const float* cp = coords + (size_t)ga * 3;
        float x = cp[0], y = cp[1], z = cp[2];
        if (species[ga] == -1) {
            const float nanv = __int_as_float(0x7fc00000);
            x = nanv; y = nanv; z = nanv;
        }
        s4[a + (a >> 5)] = make_float4(x, y, z, 0.0f);
    }
    __syncthreads();

    // ---- my two row coordinates ----
    const float4 ci0 = s4[iloc0 + (iloc0 >> 5)];
    const float4 ci1 = s4[iloc1 + (iloc1 >> 5)];
    const unsigned valid0 = valid_mask(iloc0, c);
    const unsigned valid1 = valid_mask(iloc1, c);

    // ---- phase A: 32 LDS.128, 64 pair tests -> two register bitmasks ----
    unsigned mask0 = 0u, mask1 = 0u;
    const int sbase = c * 33;         // padded chunk base (conflict-free)
#pragma unroll 4
    for (int l = 0; l < 32; l++) {
        const float4 cj = s4[sbase + l];
        {
            float dx = ci0.x - cj.x, dy = ci0.y - cj.y, dz = ci0.z - cj.z;
            float d2 = fmaf(dz, dz, fmaf(dy, dy, dx * dx));
            mask0 |= ((unsigned)(d2 <= C2_EXACT)) << l;   // NaN -> false
        }
        {
            float dx = ci1.x - cj.x, dy = ci1.y - cj.y, dz = ci1.z - cj.z;
            float d2 = fmaf(dz, dz, fmaf(dy, dy, dx * dx));
            mask1 |= ((unsigned)(d2 <= C2_EXACT)) << l;
        }
    }
    mask0 &= valid0;
    mask1 &= valid1;

    // ---- per-row counts + block-local exclusive row offsets (64 rows) ----
    const int pc0 = __popc(mask0);
    const int pc1 = __popc(mask1);
    const int rs0 = __reduce_add_sync(FULL, pc0);
    const int rs1 = __reduce_add_sync(FULL, pc1);
    if (c == 0) { s_rowCnt[2 * w] = rs0; s_rowCnt[2 * w + 1] = rs1; }
    __syncthreads();
    if (w == 0) {
        const int v0 = s_rowCnt[c];
        const int e0 = warp_excl_scan(v0, c);
        const int t0 = __shfl_sync(FULL, e0 + v0, 31);   // total rows 0..31
        const int v1 = s_rowCnt[32 + c];
        const int e1 = warp_excl_scan(v1, c);
        s_rowOff[c] = e0;
        s_rowOff[32 + c] = t0 + e1;
        if (c == 31) {
            g_blkSum[b] = t0 + e1 + v1;   // block total
            __threadfence();              // visible before barrier arrive
        }
    }
    __syncthreads();

    // ---- hoist emit prefix work (independent of barrier results) ----
    const int pre_o0 = s_rowOff[2 * w] + warp_excl_scan(pc0, c);
    const int pre_o1 = s_rowOff[2 * w + 1] + warp_excl_scan(pc1, c);

    // ---- grid barrier (monotonic epoch: safe across graph replays) ----
    if (tid == 0) {
        unsigned my = atomicAdd(&g_arrive, 1);
        unsigned target = my + 1;
        if ((target & (NBLK - 1)) == 0u)   // last arrival of this launch
            atomicAdd(&g_epoch, 1);
        while ((int)(NBLK * (*(volatile unsigned*)&g_epoch) - target) < 0)
            __nanosleep(32);
        __threadfence();
    }
    __syncthreads();

    // ---- phase B: every warp redundantly reduces the 128 block sums ----
    int bsum = 0, tsum = 0;
#pragma unroll
    for (int q = 0; q < NBLK / 32; q++) {
        const int k = q * 32 + c;
        const int v = __ldcg(&g_blkSum[k]);
        tsum += v;
        if (k < b) bsum += v;
    }
    const int blockBase = __reduce_add_sync(FULL, bsum);
    const int total = __reduce_add_sync(FULL, tsum);

    // ---- phase C: emit pairs (two rows per warp) ----
    const int jb = mb + c * 32;
    if (mask0) {
        int o = blockBase + pre_o0;
        const float rowf = (float)grow0;
        unsigned mm = mask0;
        while (mm) {
            const int l = __ffs(mm) - 1;
            mm &= mm - 1;
            out[o] = rowf;
            out[total + o] = (float)(jb + l);
            o++;
        }
    }
    if (mask1) {
        int o = blockBase + pre_o1;
        const float rowf = (float)(grow0 + 1);
        unsigned mm = mask1;
        while (mm) {
            const int l = __ffs(mm) - 1;
            mm &= mm - 1;
            out[o] = rowf;
            out[total + o] = (float)(jb + l);
            o++;
        }
    }

    // ---- tail: zero past the 2*P payload (covers the zeros(3) output) ----
    const int gtid = b * NTHR + tid;
    for (int idx = gtid; idx < out_size; idx += NBLK * NTHR)
        if (idx >= 2 * total) out[idx] = 0.0f;
}

extern "C" void kernel_launch(void* const* d_in, const int* in_sizes, int n_in,
                              void* d_out, int out_size) {
    const int* species = (const int*)d_in[0];
    const float* coords = (const float*)d_in[1];
    float* out = (float*)d_out;

    fused_kernel<<<NBLK, NTHR>>>(species, coords, out, out_size);
}